// round 6
// baseline (speedup 1.0000x reference)
#include <cuda_runtime.h>
#include <math.h>

#define NG   5000
#define IMH  512
#define IMW  512
#define HW   (IMH * IMW)

// ---------------------------------------------------------------------------
// Kernel 1: zero the output image (d_out is poisoned to 0xAA by the harness).
// 786432 floats = 196608 float4.
// ---------------------------------------------------------------------------
__global__ void zero_kernel(float4* __restrict__ out4, int n4) {
    int i = blockIdx.x * blockDim.x + threadIdx.x;
    if (i < n4) out4[i] = make_float4(0.f, 0.f, 0.f, 0.f);
}

// ---------------------------------------------------------------------------
// Kernel 2: splat. One warp per gaussian. All 32 lanes redundantly compute
// the per-gaussian parameters (cheap), then stride the bounding-box pixels.
// ---------------------------------------------------------------------------
__global__ void __launch_bounds__(256)
splat_kernel(const float* __restrict__ xyz,
             const float* __restrict__ scaling,
             const float* __restrict__ rot,
             const float* __restrict__ feat,
             const float* __restrict__ opac,
             float* __restrict__ out) {
    const int g    = (blockIdx.x * blockDim.x + threadIdx.x) >> 5;
    const int lane = threadIdx.x & 31;
    if (g >= NG) return;

    // ---- per-gaussian parameters (match reference math) ----
    const float mx = tanhf(xyz[2 * g + 0]);
    const float my = tanhf(xyz[2 * g + 1]);
    const float sx = fabsf(scaling[2 * g + 0] + 0.5f);
    const float sy = fabsf(scaling[2 * g + 1] + 0.5f);
    const float theta = (1.0f / (1.0f + expf(-rot[g]))) * 6.283185307179586f;

    const float cx = 0.5f * ((mx + 1.0f) * (float)IMW - 1.0f);
    const float cy = 0.5f * ((my + 1.0f) * (float)IMH - 1.0f);

    float sth, cth;
    sincosf(theta, &sth, &cth);
    const float sx2 = sx * sx;
    const float sy2 = sy * sy;
    const float a = cth * cth * sx2 + sth * sth * sy2;   // covariance xx
    const float b = cth * sth * (sx2 - sy2);             // covariance xy
    const float c = sth * sth * sx2 + cth * cth * sy2;   // covariance yy
    const float det = a * c - b * b;
    if (!(det > 0.0f)) return;                           // valid check
    const float inv_det = 1.0f / fmaxf(det, 1e-12f);
    const float A =  c * inv_det;                        // inv-cov xx
    const float B = -b * inv_det;                        // inv-cov xy
    const float C =  a * inv_det;                        // inv-cov yy

    const float op = opac[g];
    if (!(op > 1.0f / 255.0f)) return;                   // alpha can never pass
    // alpha = op*exp(-sigma) > 1/255  <=>  sigma < ln(255*op)
    const float smax = logf(255.0f * op);
    if (!(smax > 0.0f)) return;

    // Axis-aligned extents of the ellipse {d : d^T Sigma^-1 d <= 2*smax}:
    // |dx|max = sqrt(2*smax*Sigma_xx), |dy|max = sqrt(2*smax*Sigma_yy)
    const float dxm = sqrtf(2.0f * smax * a);
    const float dym = sqrtf(2.0f * smax * c);

    const int x0 = max(0,       (int)ceilf (cx - dxm));
    const int x1 = min(IMW - 1, (int)floorf(cx + dxm));
    const int y0 = max(0,       (int)ceilf (cy - dym));
    const int y1 = min(IMH - 1, (int)floorf(cy + dym));
    if (x0 > x1 || y0 > y1) return;

    const int w    = x1 - x0 + 1;
    const int npix = w * (y1 - y0 + 1);

    const float cr = feat[3 * g + 0];
    const float cg = feat[3 * g + 1];
    const float cb = feat[3 * g + 2];

    for (int i = lane; i < npix; i += 32) {
        const int px = x0 + (i % w);
        const int py = y0 + (i / w);
        const float dx = cx - (float)px;
        const float dy = cy - (float)py;
        const float sigma = 0.5f * (A * dx * dx + C * dy * dy) + B * dx * dy;
        const float alpha = op * expf(-sigma);
        if (sigma >= 0.0f && alpha > 1.0f / 255.0f) {
            const int p = py * IMW + px;
            atomicAdd(&out[p],           alpha * cr);
            atomicAdd(&out[HW + p],      alpha * cg);
            atomicAdd(&out[2 * HW + p],  alpha * cb);
        }
    }
}

// ---------------------------------------------------------------------------
// Kernel 3: clamp to [0,1] in place.
// ---------------------------------------------------------------------------
__global__ void clamp_kernel(float4* __restrict__ out4, int n4) {
    int i = blockIdx.x * blockDim.x + threadIdx.x;
    if (i < n4) {
        float4 v = out4[i];
        v.x = fminf(fmaxf(v.x, 0.f), 1.f);
        v.y = fminf(fmaxf(v.y, 0.f), 1.f);
        v.z = fminf(fmaxf(v.z, 0.f), 1.f);
        v.w = fminf(fmaxf(v.w, 0.f), 1.f);
        out4[i] = v;
    }
}

// ---------------------------------------------------------------------------
// Launch wrapper (graph-capturable: kernel launches only, no allocs/syncs)
// Inputs (metadata order): _xyz(N,2) _scaling(N,2) _rotation(N,1)
//                          _features_dc(N,3) _opacity(N,1)
// Output: float32 (1,3,512,512)
// ---------------------------------------------------------------------------
extern "C" void kernel_launch(void* const* d_in, const int* in_sizes, int n_in,
                              void* d_out, int out_size) {
    const float* xyz     = (const float*)d_in[0];
    const float* scaling = (const float*)d_in[1];
    const float* rot     = (const float*)d_in[2];
    const float* feat    = (const float*)d_in[3];
    const float* opac    = (const float*)d_in[4];
    float* out = (float*)d_out;

    const int n4 = (3 * HW) / 4;                 // 589824... wait: 3*262144/4
    // 3*HW = 786432 floats -> 196608 float4
    zero_kernel<<<(n4 + 255) / 256, 256>>>((float4*)out, n4);

    const int total_threads = NG * 32;           // one warp per gaussian
    splat_kernel<<<(total_threads + 255) / 256, 256>>>(xyz, scaling, rot, feat,
                                                       opac, out);

    clamp_kernel<<<(n4 + 255) / 256, 256>>>((float4*)out, n4);
}